// round 1
// baseline (speedup 1.0000x reference)
#include <cuda_runtime.h>
#include <cuda_bf16.h>
#include <math.h>

#define NN 50000
#define EE 800000
#define DIN 128
#define H1 256
#define H2 128
#define NG 64

// ---------------- device scratch (static, allocation-free) ----------------
__device__ int   g_deg[NN];
__device__ int   g_rowptr[NN + 1];
__device__ int   g_cur[NN];
__device__ int   g_csrc[EE];
__device__ float g_mean0[NN * DIN];
__device__ float g_out0[NN * H1];
__device__ float g_res0[NN * H1];
__device__ float g_h[NN * H1];
__device__ float g_tuw[NN * 384];   // cols 0-127: t=h@Wl1, 128-255: u=h@Wr1+bl1, 256-383: res1=h@Wp1+bp1
__device__ float g_out1[NN * H2];
__device__ float g_sum0[H1], g_sq0[H1], g_sum1[H2], g_sq1[H2];
__device__ float g_a0[H1], g_b0[H1], g_a1[H2], g_b1[H2];
__device__ float g_embsum[NG * H2];
__device__ float g_gcnt[NG];
__device__ float g_emb[NG * H2];
__device__ float g_z0[NG * 256];
__device__ float g_z1[NG * 128];

// ---------------- init / CSR build ----------------
__global__ void k_zero() {
    int i = blockIdx.x * blockDim.x + threadIdx.x;
    int stride = gridDim.x * blockDim.x;
    for (int t = i; t < NN; t += stride) g_deg[t] = 0;
    for (int t = i; t < H1; t += stride) { g_sum0[t] = 0.f; g_sq0[t] = 0.f; }
    for (int t = i; t < H2; t += stride) { g_sum1[t] = 0.f; g_sq1[t] = 0.f; }
    for (int t = i; t < NG * H2; t += stride) g_embsum[t] = 0.f;
    for (int t = i; t < NG; t += stride) g_gcnt[t] = 0.f;
}

__global__ void k_count(const int* __restrict__ ei) {
    const int* dst = ei + EE;
    int i = blockIdx.x * blockDim.x + threadIdx.x;
    int stride = gridDim.x * blockDim.x;
    for (int e = i; e < EE; e += stride) atomicAdd(&g_deg[dst[e]], 1);
}

__global__ void k_scan() {
    __shared__ int wsum[32];
    __shared__ int carry;
    int tid = threadIdx.x, lane = tid & 31, w = tid >> 5;
    if (tid == 0) carry = 0;
    __syncthreads();
    for (int base = 0; base < NN; base += 1024) {
        int idx = base + tid;
        int v = (idx < NN) ? g_deg[idx] : 0;
        int s = v;
#pragma unroll
        for (int o = 1; o < 32; o <<= 1) {
            int n = __shfl_up_sync(0xffffffffu, s, o);
            if (lane >= o) s += n;
        }
        if (lane == 31) wsum[w] = s;
        __syncthreads();
        if (w == 0) {
            int t = wsum[lane];
#pragma unroll
            for (int o = 1; o < 32; o <<= 1) {
                int n = __shfl_up_sync(0xffffffffu, t, o);
                if (lane >= o) t += n;
            }
            wsum[lane] = t;
        }
        __syncthreads();
        int incl = s + (w > 0 ? wsum[w - 1] : 0);
        int excl = incl - v + carry;
        if (idx < NN) { g_rowptr[idx] = excl; g_cur[idx] = excl; }
        __syncthreads();
        if (tid == 1023) carry += incl;
        __syncthreads();
    }
    if (tid == 0) g_rowptr[NN] = carry;
}

__global__ void k_fill(const int* __restrict__ ei) {
    const int* src = ei;
    const int* dst = ei + EE;
    int i = blockIdx.x * blockDim.x + threadIdx.x;
    int stride = gridDim.x * blockDim.x;
    for (int e = i; e < EE; e += stride) {
        int d = dst[e];
        int slot = atomicAdd(&g_cur[d], 1);
        g_csrc[slot] = src[e];
    }
}

// ---------------- aggregation ----------------
// layer 0: mean over in-neighbors of x (128 dims). block = node, 128 threads.
__global__ void k_agg0(const float* __restrict__ x) {
    int r = blockIdx.x;
    int j = threadIdx.x;
    int s = g_rowptr[r], e = g_rowptr[r + 1];
    __shared__ int sh[256];
    float acc = 0.f;
    for (int p0 = s; p0 < e; p0 += 256) {
        int cnt = min(e - p0, 256);
        for (int q = j; q < cnt; q += 128) sh[q] = g_csrc[p0 + q];
        __syncthreads();
        for (int q = 0; q < cnt; q++) acc += x[sh[q] * DIN + j];
        __syncthreads();
    }
    float d = (float)max(e - s, 1);
    g_mean0[r * DIN + j] = acc / d;
}

// layer 1: aggregate t=h@Wl1 (128 dims), add u, L2-normalize row, store out1.
__global__ void k_agg1() {
    int r = blockIdx.x;
    int j = threadIdx.x; // 128
    int s = g_rowptr[r], e = g_rowptr[r + 1];
    __shared__ int sh[256];
    __shared__ float wred[4];
    float acc = 0.f;
    for (int p0 = s; p0 < e; p0 += 256) {
        int cnt = min(e - p0, 256);
        for (int q = j; q < cnt; q += 128) sh[q] = g_csrc[p0 + q];
        __syncthreads();
        for (int q = 0; q < cnt; q++) acc += g_tuw[sh[q] * 384 + j];
        __syncthreads();
    }
    float d = (float)max(e - s, 1);
    float v = acc / d + g_tuw[r * 384 + 128 + j];
    float q = v * v;
#pragma unroll
    for (int o = 16; o > 0; o >>= 1) q += __shfl_xor_sync(0xffffffffu, q, o);
    int lane = j & 31, w = j >> 5;
    if (lane == 0) wred[w] = q;
    __syncthreads();
    float tot = wred[0] + wred[1] + wred[2] + wred[3];
    float inv = 1.f / fmaxf(sqrtf(tot), 1e-12f);
    g_out1[r * H2 + j] = v * inv;
}

// ---------------- GEMM: C = A0@W0 + A1@W1 + bias ----------------
// 128x128 block tile, BK=16, 8x8 register tile, 256 threads.
__global__ __launch_bounds__(256) void k_gemm(
    const float* __restrict__ A0, const float* __restrict__ W0, int K0,
    const float* __restrict__ A1, const float* __restrict__ W1, int K1,
    const float* __restrict__ bias, float* __restrict__ C,
    int M, int ncols, int ldc)
{
    const int BM = 128, BN = 128, BK = 16;
    __shared__ float As[BK][BM];
    __shared__ float Ws[BK][BN];
    int tid = threadIdx.x;
    int row0 = blockIdx.y * BM;
    int col0 = blockIdx.x * BN;
    int warp = tid >> 5, lane = tid & 31;
    int ty = (warp >> 2) * 8 + (lane >> 2);  // 0..15 (8 per warp -> 2-way LDS bcast groups)
    int tx = (warp & 3) * 4 + (lane & 3);    // 0..15

    float acc[8][8];
#pragma unroll
    for (int i = 0; i < 8; i++)
#pragma unroll
        for (int j = 0; j < 8; j++) acc[i][j] = 0.f;

    const float* Ap = A0; const float* Wp = W0; int K = K0;
    for (int pair = 0; pair < 2; ++pair) {
        if (pair == 1) { Ap = A1; Wp = W1; K = K1; }
        if (K <= 0 || Ap == nullptr) continue;
        for (int k0 = 0; k0 < K; k0 += BK) {
#pragma unroll
            for (int i = 0; i < 2; i++) {
                int f = tid + i * 256;
                int ar = f >> 2, ac = f & 3;
                int grow = row0 + ar;
                float4 v = make_float4(0.f, 0.f, 0.f, 0.f);
                if (grow < M)
                    v = *reinterpret_cast<const float4*>(Ap + (size_t)grow * K + k0 + ac * 4);
                As[ac * 4 + 0][ar] = v.x;
                As[ac * 4 + 1][ar] = v.y;
                As[ac * 4 + 2][ar] = v.z;
                As[ac * 4 + 3][ar] = v.w;
            }
#pragma unroll
            for (int i = 0; i < 2; i++) {
                int f = tid + i * 256;
                int wr = f >> 5, wc = f & 31;
                float4 v = *reinterpret_cast<const float4*>(Wp + (size_t)(k0 + wr) * ncols + col0 + wc * 4);
                *reinterpret_cast<float4*>(&Ws[wr][wc * 4]) = v;
            }
            __syncthreads();
#pragma unroll
            for (int kk = 0; kk < BK; kk++) {
                float a[8], b[8];
                *(float4*)&a[0] = *(float4*)&As[kk][ty * 8];
                *(float4*)&a[4] = *(float4*)&As[kk][ty * 8 + 4];
                *(float4*)&b[0] = *(float4*)&Ws[kk][tx * 8];
                *(float4*)&b[4] = *(float4*)&Ws[kk][tx * 8 + 4];
#pragma unroll
                for (int i = 0; i < 8; i++)
#pragma unroll
                    for (int j = 0; j < 8; j++) acc[i][j] += a[i] * b[j];
            }
            __syncthreads();
        }
    }
#pragma unroll
    for (int i = 0; i < 8; i++) {
        int r = row0 + ty * 8 + i;
        if (r >= M) continue;
#pragma unroll
        for (int j0 = 0; j0 < 8; j0 += 4) {
            int c = col0 + tx * 8 + j0;
            float4 v;
            v.x = acc[i][j0 + 0]; v.y = acc[i][j0 + 1];
            v.z = acc[i][j0 + 2]; v.w = acc[i][j0 + 3];
            if (bias) { v.x += bias[c]; v.y += bias[c + 1]; v.z += bias[c + 2]; v.w += bias[c + 3]; }
            *reinterpret_cast<float4*>(C + (size_t)r * ldc + c) = v;
        }
    }
}

// ---------------- row L2 norm (layer 0, 256-wide rows, in place) ----------------
__global__ void k_rownorm0() {
    int r = blockIdx.x, j = threadIdx.x; // 256 threads
    __shared__ float wred[8];
    float v = g_out0[r * H1 + j];
    float q = v * v;
#pragma unroll
    for (int o = 16; o > 0; o >>= 1) q += __shfl_xor_sync(0xffffffffu, q, o);
    int lane = j & 31, w = j >> 5;
    if (lane == 0) wred[w] = q;
    __syncthreads();
    float tot = 0.f;
#pragma unroll
    for (int i = 0; i < 8; i++) tot += wred[i];
    float inv = 1.f / fmaxf(sqrtf(tot), 1e-12f);
    g_out0[r * H1 + j] = v * inv;
}

// ---------------- batchnorm: column stats -> (a,b) -> apply ----------------
__global__ void k_colstats(const float* __restrict__ C, int cols,
                           float* __restrict__ sum, float* __restrict__ sq) {
    int j = threadIdx.x;   // blockDim.x == cols
    float s = 0.f, q = 0.f;
    for (int r = blockIdx.x; r < NN; r += gridDim.x) {
        float v = C[r * cols + j];
        s += v; q += v * v;
    }
    atomicAdd(&sum[j], s);
    atomicAdd(&sq[j], q);
}

__global__ void k_bnprep(const float* __restrict__ g, const float* __restrict__ be,
                         const float* __restrict__ sum, const float* __restrict__ sq,
                         float* __restrict__ a, float* __restrict__ b, int cols) {
    int j = threadIdx.x;
    if (j < cols) {
        float mu = sum[j] / (float)NN;
        float var = sq[j] / (float)NN - mu * mu;
        float s = g[j] * rsqrtf(var + 1e-5f);
        a[j] = s;
        b[j] = be[j] - mu * s;
    }
}

__global__ void k_bnapply0() {
    int i = blockIdx.x * blockDim.x + threadIdx.x;
    int stride = gridDim.x * blockDim.x;
    for (int t = i; t < NN * H1; t += stride) {
        int j = t & (H1 - 1);
        float v = g_a0[j] * g_out0[t] + g_b0[j];
        g_h[t] = fmaxf(v, 0.f) + g_res0[t];
    }
}

__global__ void k_gcnt(const int* __restrict__ batch) {
    int i = blockIdx.x * blockDim.x + threadIdx.x;
    int stride = gridDim.x * blockDim.x;
    for (int t = i; t < NN; t += stride) atomicAdd(&g_gcnt[batch[t]], 1.f);
}

// BN+relu+residual for layer 1, fused with mean-pool accumulation.
__global__ void k_bnapply1(const int* __restrict__ batch) {
    int i = blockIdx.x * blockDim.x + threadIdx.x;
    int stride = gridDim.x * blockDim.x;
    for (int t = i; t < NN * H2; t += stride) {
        int r = t >> 7, j = t & 127;
        float v = fmaxf(g_a1[j] * g_out1[t] + g_b1[j], 0.f) + g_tuw[r * 384 + 256 + j];
        atomicAdd(&g_embsum[batch[r] * H2 + j], v);
    }
}

// ---------------- pool finalize + classifier MLP (single block) ----------------
__global__ __launch_bounds__(256) void k_classifier(
    const float* __restrict__ Wc0, const float* __restrict__ bc0,
    const float* __restrict__ gc0, const float* __restrict__ bec0,
    const float* __restrict__ Wc1, const float* __restrict__ bc1,
    const float* __restrict__ gc1, const float* __restrict__ bec1,
    const float* __restrict__ Wc2, const float* __restrict__ bc2,
    float* __restrict__ out)
{
    int tid = threadIdx.x;
    // finalize emb = sum / max(cnt,1); emb occupies out[128 .. 128+8192)
    for (int t = tid; t < NG * H2; t += 256) {
        int gi = t >> 7;
        float c = fmaxf(g_gcnt[gi], 1.f);
        float v = g_embsum[t] / c;
        g_emb[t] = v;
        out[NG * 2 + t] = v;
    }
    __syncthreads();
    // z0 = relu(BN(emb@Wc0 + bc0)) ; each thread owns one of 256 columns
    {
        int c = tid;
        float vals[64];
        float mu = 0.f, sq = 0.f;
#pragma unroll 4
        for (int r = 0; r < NG; r++) {
            float acc = bc0[c];
            for (int k = 0; k < H2; k++) acc += g_emb[r * H2 + k] * Wc0[k * 256 + c];
            vals[r] = acc; mu += acc; sq += acc * acc;
        }
        mu *= (1.f / NG);
        float var = sq * (1.f / NG) - mu * mu;
        float a = gc0[c] * rsqrtf(var + 1e-5f);
        float b = bec0[c] - mu * a;
        for (int r = 0; r < NG; r++) g_z0[r * 256 + c] = fmaxf(a * vals[r] + b, 0.f);
    }
    __syncthreads();
    // z1 = relu(BN(z0@Wc1 + bc1)) ; 128 columns
    if (tid < 128) {
        int c = tid;
        float vals[64];
        float mu = 0.f, sq = 0.f;
#pragma unroll 4
        for (int r = 0; r < NG; r++) {
            float acc = bc1[c];
            for (int k = 0; k < 256; k++) acc += g_z0[r * 256 + k] * Wc1[k * 128 + c];
            vals[r] = acc; mu += acc; sq += acc * acc;
        }
        mu *= (1.f / NG);
        float var = sq * (1.f / NG) - mu * mu;
        float a = gc1[c] * rsqrtf(var + 1e-5f);
        float b = bec1[c] - mu * a;
        for (int r = 0; r < NG; r++) g_z1[r * 128 + c] = fmaxf(a * vals[r] + b, 0.f);
    }
    __syncthreads();
    // logits = z1@Wc2 + bc2 -> out[0 .. 128)
    if (tid < NG * 2) {
        int gi = tid >> 1, c = tid & 1;
        float acc = bc2[c];
        for (int k = 0; k < 128; k++) acc += g_z1[gi * 128 + k] * Wc2[k * 2 + c];
        out[gi * 2 + c] = acc;
    }
}

// ---------------- launch ----------------
extern "C" void kernel_launch(void* const* d_in, const int* in_sizes, int n_in,
                              void* d_out, int out_size) {
    const float* x    = (const float*)d_in[0];
    const int*   ei   = (const int*)d_in[1];
    const int*   batch= (const int*)d_in[2];
    const float* Wl0  = (const float*)d_in[3];
    const float* bl0  = (const float*)d_in[4];
    const float* Wr0  = (const float*)d_in[5];
    const float* g0   = (const float*)d_in[6];
    const float* be0  = (const float*)d_in[7];
    const float* Wl1  = (const float*)d_in[8];
    const float* bl1  = (const float*)d_in[9];
    const float* Wr1  = (const float*)d_in[10];
    const float* g1   = (const float*)d_in[11];
    const float* be1  = (const float*)d_in[12];
    const float* Wp0  = (const float*)d_in[13];
    const float* bp0  = (const float*)d_in[14];
    const float* Wp1  = (const float*)d_in[15];
    const float* bp1  = (const float*)d_in[16];
    const float* Wc0  = (const float*)d_in[17];
    const float* bc0  = (const float*)d_in[18];
    const float* gc0  = (const float*)d_in[19];
    const float* bec0 = (const float*)d_in[20];
    const float* Wc1  = (const float*)d_in[21];
    const float* bc1  = (const float*)d_in[22];
    const float* gc1  = (const float*)d_in[23];
    const float* bec1 = (const float*)d_in[24];
    const float* Wc2  = (const float*)d_in[25];
    const float* bc2  = (const float*)d_in[26];
    float* out = (float*)d_out;

    float *p_mean0, *p_out0, *p_res0, *p_h, *p_tuw, *p_out1;
    float *p_sum0, *p_sq0, *p_sum1, *p_sq1, *p_a0, *p_b0, *p_a1, *p_b1;
    cudaGetSymbolAddress((void**)&p_mean0, g_mean0);
    cudaGetSymbolAddress((void**)&p_out0, g_out0);
    cudaGetSymbolAddress((void**)&p_res0, g_res0);
    cudaGetSymbolAddress((void**)&p_h, g_h);
    cudaGetSymbolAddress((void**)&p_tuw, g_tuw);
    cudaGetSymbolAddress((void**)&p_out1, g_out1);
    cudaGetSymbolAddress((void**)&p_sum0, g_sum0);
    cudaGetSymbolAddress((void**)&p_sq0, g_sq0);
    cudaGetSymbolAddress((void**)&p_sum1, g_sum1);
    cudaGetSymbolAddress((void**)&p_sq1, g_sq1);
    cudaGetSymbolAddress((void**)&p_a0, g_a0);
    cudaGetSymbolAddress((void**)&p_b0, g_b0);
    cudaGetSymbolAddress((void**)&p_a1, g_a1);
    cudaGetSymbolAddress((void**)&p_b1, g_b1);

    const int rowBlocks = (NN + 127) / 128;

    k_zero<<<256, 256>>>();
    k_count<<<3125, 256>>>(ei);
    k_scan<<<1, 1024>>>();
    k_fill<<<3125, 256>>>(ei);

    // layer 0
    k_agg0<<<NN, 128>>>(x);
    k_gemm<<<dim3(2, rowBlocks), 256>>>(p_mean0, Wl0, DIN, x, Wr0, DIN, bl0, p_out0, NN, H1, H1);
    k_gemm<<<dim3(2, rowBlocks), 256>>>(x, Wp0, DIN, nullptr, nullptr, 0, bp0, p_res0, NN, H1, H1);
    k_rownorm0<<<NN, 256>>>();
    k_colstats<<<512, H1>>>(p_out0, H1, p_sum0, p_sq0);
    k_bnprep<<<1, 256>>>(g0, be0, p_sum0, p_sq0, p_a0, p_b0, H1);
    k_bnapply0<<<2048, 256>>>();

    // layer 1 (GEMM-first trick: aggregate in 128-dim space)
    k_gemm<<<dim3(1, rowBlocks), 256>>>(p_h, Wl1, H1, nullptr, nullptr, 0, nullptr, p_tuw + 0,   NN, H2, 384);
    k_gemm<<<dim3(1, rowBlocks), 256>>>(p_h, Wr1, H1, nullptr, nullptr, 0, bl1,     p_tuw + 128, NN, H2, 384);
    k_gemm<<<dim3(1, rowBlocks), 256>>>(p_h, Wp1, H1, nullptr, nullptr, 0, bp1,     p_tuw + 256, NN, H2, 384);
    k_agg1<<<NN, 128>>>();
    k_colstats<<<512, H2>>>(p_out1, H2, p_sum1, p_sq1);
    k_bnprep<<<1, 128>>>(g1, be1, p_sum1, p_sq1, p_a1, p_b1, H2);

    // pool (fused into BN apply) + classifier
    k_gcnt<<<196, 256>>>(batch);
    k_bnapply1<<<2048, 256>>>(batch);
    k_classifier<<<1, 256>>>(Wc0, bc0, gc0, bec0, Wc1, bc1, gc1, bec1, Wc2, bc2, out);
}

// round 4
// speedup vs baseline: 1.2907x; 1.2907x over previous
#include <cuda_runtime.h>
#include <cuda_bf16.h>
#include <cstdint>
#include <stdint.h>
#include <math.h>

#define NN 50000
#define EE 800000
#define DIN 128
#define H1 256
#define H2 128
#define NG 64

// ---------------- device scratch (static, allocation-free) ----------------
__device__ int   g_deg[NN];
__device__ int   g_rowptr[NN + 1];
__device__ int   g_cur[NN];
__device__ int   g_csrc[EE];

// bf16-split activation buffers
__device__ __nv_bfloat16 g_A0h[NN * 256];   // cols 0-127: mean0, 128-255: x
__device__ __nv_bfloat16 g_A0l[NN * 256];
__device__ __nv_bfloat16 g_Hh[NN * 256];    // h (layer-0 output)
__device__ __nv_bfloat16 g_Hl[NN * 256];

// bf16-split weights (prepped each call)
__device__ __nv_bfloat16 g_W0h[256 * 256];
__device__ __nv_bfloat16 g_W0l[256 * 256];
__device__ __nv_bfloat16 g_Wp0h[128 * 256];
__device__ __nv_bfloat16 g_Wp0l[128 * 256];
__device__ __nv_bfloat16 g_W1h[256 * 384];
__device__ __nv_bfloat16 g_W1l[256 * 384];
__device__ float g_bias1[384];

// fp32 intermediates
__device__ float g_out0[NN * H1];
__device__ float g_res0[NN * H1];
__device__ float g_tuw[NN * 384];   // 0-127: t, 128-255: u, 256-383: res1
__device__ float g_out1[NN * H2];
__device__ float g_sum0[H1];
__device__ float g_sq0[H1];
__device__ float g_sum1[H2];
__device__ float g_sq1[H2];
__device__ float g_a0[H1];
__device__ float g_b0[H1];
__device__ float g_a1[H2];
__device__ float g_b1[H2];
__device__ float g_embsum[NG * H2];
__device__ float g_gcnt[NG];
__device__ float g_emb[NG * H2];
__device__ float g_z0[NG * 256];
__device__ float g_z1[NG * 128];

__device__ __forceinline__ void split_bf16(float v, __nv_bfloat16& h, __nv_bfloat16& l) {
    h = __float2bfloat16(v);
    l = __float2bfloat16(v - __bfloat162float(h));
}

// ---------------- init / CSR build ----------------
__global__ void k_zero() {
    int i = blockIdx.x * blockDim.x + threadIdx.x;
    int stride = gridDim.x * blockDim.x;
    for (int t = i; t < NN; t += stride) g_deg[t] = 0;
    for (int t = i; t < H1; t += stride) { g_sum0[t] = 0.f; g_sq0[t] = 0.f; }
    for (int t = i; t < H2; t += stride) { g_sum1[t] = 0.f; g_sq1[t] = 0.f; }
    for (int t = i; t < NG * H2; t += stride) g_embsum[t] = 0.f;
    for (int t = i; t < NG; t += stride) g_gcnt[t] = 0.f;
}

__global__ void k_count(const int* __restrict__ ei) {
    const int* dst = ei + EE;
    int i = blockIdx.x * blockDim.x + threadIdx.x;
    int stride = gridDim.x * blockDim.x;
    for (int e = i; e < EE; e += stride) atomicAdd(&g_deg[dst[e]], 1);
}

__global__ void k_scan() {
    __shared__ int wsum[32];
    __shared__ int carry;
    int tid = threadIdx.x, lane = tid & 31, w = tid >> 5;
    if (tid == 0) carry = 0;
    __syncthreads();
    for (int base = 0; base < NN; base += 1024) {
        int idx = base + tid;
        int v = (idx < NN) ? g_deg[idx] : 0;
        int s = v;
#pragma unroll
        for (int o = 1; o < 32; o <<= 1) {
            int n = __shfl_up_sync(0xffffffffu, s, o);
            if (lane >= o) s += n;
        }
        if (lane == 31) wsum[w] = s;
        __syncthreads();
        if (w == 0) {
            int t = wsum[lane];
#pragma unroll
            for (int o = 1; o < 32; o <<= 1) {
                int n = __shfl_up_sync(0xffffffffu, t, o);
                if (lane >= o) t += n;
            }
            wsum[lane] = t;
        }
        __syncthreads();
        int incl = s + (w > 0 ? wsum[w - 1] : 0);
        int excl = incl - v + carry;
        if (idx < NN) { g_rowptr[idx] = excl; g_cur[idx] = excl; }
        __syncthreads();
        if (tid == 1023) carry += incl;
        __syncthreads();
    }
    if (tid == 0) g_rowptr[NN] = carry;
}

__global__ void k_fill(const int* __restrict__ ei) {
    const int* src = ei;
    const int* dst = ei + EE;
    int i = blockIdx.x * blockDim.x + threadIdx.x;
    int stride = gridDim.x * blockDim.x;
    for (int e = i; e < EE; e += stride) {
        int d = dst[e];
        int slot = atomicAdd(&g_cur[d], 1);
        g_csrc[slot] = src[e];
    }
}

// ---------------- weight prep: fp32 -> bf16 hi/lo, concatenated layouts ----------------
__global__ void k_prep_weights(
    const float* __restrict__ Wl0, const float* __restrict__ Wr0,
    const float* __restrict__ Wp0,
    const float* __restrict__ Wl1, const float* __restrict__ Wr1,
    const float* __restrict__ Wp1,
    const float* __restrict__ bl1, const float* __restrict__ bp1)
{
    int i = blockIdx.x * blockDim.x + threadIdx.x;
    int stride = gridDim.x * blockDim.x;
    const int T0 = 256 * 256;
    const int T1 = 128 * 256;
    const int T2 = 256 * 384;
    for (int t = i; t < T0 + T1 + T2; t += stride) {
        if (t < T0) {
            int r = t >> 8;
            int c = t & 255;
            float v = (r < 128) ? Wl0[r * 256 + c] : Wr0[(r - 128) * 256 + c];
            split_bf16(v, g_W0h[t], g_W0l[t]);
        } else if (t < T0 + T1) {
            int j = t - T0;
            split_bf16(Wp0[j], g_Wp0h[j], g_Wp0l[j]);
        } else {
            int j = t - T0 - T1;
            int r = j / 384;
            int c = j % 384;
            float v;
            if (c < 128) v = Wl1[r * 128 + c];
            else if (c < 256) v = Wr1[r * 128 + (c - 128)];
            else v = Wp1[r * 128 + (c - 256)];
            split_bf16(v, g_W1h[j], g_W1l[j]);
        }
    }
    for (int t = i; t < 384; t += stride) {
        float v;
        if (t < 128) v = 0.f;
        else if (t < 256) v = bl1[t - 128];
        else v = bp1[t - 256];
        g_bias1[t] = v;
    }
}

// ---------------- x -> bf16 split into A0 cols 128..255 ----------------
__global__ void k_xcvt(const float* __restrict__ x) {
    int i = blockIdx.x * blockDim.x + threadIdx.x;
    int stride = gridDim.x * blockDim.x;
    for (int t = i; t < NN * 128; t += stride) {
        int r = t >> 7;
        int c = t & 127;
        split_bf16(x[t], g_A0h[r * 256 + 128 + c], g_A0l[r * 256 + 128 + c]);
    }
}

// ---------------- aggregation ----------------
__global__ void k_agg0(const float* __restrict__ x) {
    int r = blockIdx.x;
    int j = threadIdx.x;
    int s = g_rowptr[r];
    int e = g_rowptr[r + 1];
    __shared__ int sh[256];
    float acc = 0.f;
    for (int p0 = s; p0 < e; p0 += 256) {
        int cnt = min(e - p0, 256);
        for (int q = j; q < cnt; q += 128) sh[q] = g_csrc[p0 + q];
        __syncthreads();
        for (int q = 0; q < cnt; q++) acc += x[sh[q] * DIN + j];
        __syncthreads();
    }
    float d = (float)max(e - s, 1);
    split_bf16(acc / d, g_A0h[r * 256 + j], g_A0l[r * 256 + j]);
}

__global__ void k_agg1() {
    int r = blockIdx.x;
    int j = threadIdx.x; // 128
    int s = g_rowptr[r];
    int e = g_rowptr[r + 1];
    __shared__ int sh[256];
    __shared__ float wred[4];
    float acc = 0.f;
    for (int p0 = s; p0 < e; p0 += 256) {
        int cnt = min(e - p0, 256);
        for (int q = j; q < cnt; q += 128) sh[q] = g_csrc[p0 + q];
        __syncthreads();
        for (int q = 0; q < cnt; q++) acc += g_tuw[sh[q] * 384 + j];
        __syncthreads();
    }
    float d = (float)max(e - s, 1);
    float v = acc / d + g_tuw[r * 384 + 128 + j];
    float q = v * v;
#pragma unroll
    for (int o = 16; o > 0; o >>= 1) q += __shfl_xor_sync(0xffffffffu, q, o);
    int lane = j & 31;
    int w = j >> 5;
    if (lane == 0) wred[w] = q;
    __syncthreads();
    float tot = wred[0] + wred[1] + wred[2] + wred[3];
    float inv = 1.f / fmaxf(sqrtf(tot), 1e-12f);
    g_out1[r * H2 + j] = v * inv;
}

// ---------------- bf16-split tensor-core GEMM ----------------
#define A_ST 40
#define B_ST 136
#define A_STAGE_B (128 * A_ST * 2)
#define B_STAGE_B (32 * B_ST * 2)
#define SM_AL_OFF (2 * A_STAGE_B)
#define SM_BH_OFF (4 * A_STAGE_B)
#define SMEM_BYTES (SM_BH_OFF + 4 * B_STAGE_B)

__device__ __forceinline__ void cp16(unsigned int dst, const void* src, bool p) {
    int sz = p ? 16 : 0;
    asm volatile("cp.async.cg.shared.global [%0], [%1], 16, %2;\n"
                 :: "r"(dst), "l"(src), "r"(sz));
}
__device__ __forceinline__ void ldsm4(unsigned int* r, unsigned int a) {
    asm volatile("ldmatrix.sync.aligned.m8n8.x4.shared.b16 {%0,%1,%2,%3}, [%4];"
                 : "=r"(r[0]), "=r"(r[1]), "=r"(r[2]), "=r"(r[3]) : "r"(a));
}
__device__ __forceinline__ void ldsm4t(unsigned int* r, unsigned int a) {
    asm volatile("ldmatrix.sync.aligned.m8n8.x4.trans.shared.b16 {%0,%1,%2,%3}, [%4];"
                 : "=r"(r[0]), "=r"(r[1]), "=r"(r[2]), "=r"(r[3]) : "r"(a));
}
__device__ __forceinline__ void mma_bf16(float* d, const unsigned int* a, const unsigned int* b) {
    asm volatile("mma.sync.aligned.m16n8k16.row.col.f32.bf16.bf16.f32 "
                 "{%0,%1,%2,%3}, {%4,%5,%6,%7}, {%8,%9}, {%0,%1,%2,%3};"
                 : "+f"(d[0]), "+f"(d[1]), "+f"(d[2]), "+f"(d[3])
                 : "r"(a[0]), "r"(a[1]), "r"(a[2]), "r"(a[3]), "r"(b[0]), "r"(b[1]));
}

__device__ __forceinline__ void gemm_load_stage(
    unsigned int sbase, int tid, int row0, int k0, int stage,
    const __nv_bfloat16* Ah, const __nv_bfloat16* Al, int lda,
    const __nv_bfloat16* Bh, const __nv_bfloat16* Bl, int ldb, int col0)
{
#pragma unroll
    for (int i = 0; i < 2; i++) {
        int c = tid + i * 256;
        int row = c >> 2;
        int seg = c & 3;
        int gr = row0 + row;
        bool p = gr < NN;
        size_t goff = (size_t)(p ? gr : 0) * lda + k0 + seg * 8;
        unsigned int d = sbase + stage * A_STAGE_B + (unsigned int)(row * A_ST + seg * 8) * 2;
        cp16(d, Ah + goff, p);
        cp16(d + SM_AL_OFF, Al + goff, p);
    }
#pragma unroll
    for (int i = 0; i < 2; i++) {
        int c = tid + i * 256;
        int row = c >> 4;
        int seg = c & 15;
        size_t goff = (size_t)(k0 + row) * ldb + col0 + seg * 8;
        unsigned int d = sbase + SM_BH_OFF + stage * B_STAGE_B + (unsigned int)(row * B_ST + seg * 8) * 2;
        cp16(d, Bh + goff, true);
        cp16(d + 2 * B_STAGE_B, Bl + goff, true);
    }
    asm volatile("cp.async.commit_group;\n" ::: "memory");
}

// mode 0: out0  = A0 @ W0  (K=256, ldb=256, ldc=256)
// mode 1: res0  = x  @ Wp0 (K=128, ldb=256, ldc=256)
// mode 2: tuw   = H  @ W1  (K=256, ldb=384, ldc=384)
__global__ __launch_bounds__(256) void k_gemm_bf16(int mode, const float* __restrict__ bias_in) {
    extern __shared__ __align__(16) char sm[];
    const int tid = threadIdx.x;
    const int lane = tid & 31;
    const int warp = tid >> 5;
    const int wm = warp & 3;
    const int wn = warp >> 2;
    const int row0 = blockIdx.y * 128;
    const int col0 = blockIdx.x * 128;
    unsigned int sbase = (unsigned int)__cvta_generic_to_shared(sm);

    const __nv_bfloat16* Ah;
    const __nv_bfloat16* Al;
    const __nv_bfloat16* Bh;
    const __nv_bfloat16* Bl;
    const float* bias;
    float* C;
    int lda, ldb, ldc, K;
    if (mode == 0) {
        Ah = g_A0h; Al = g_A0l; lda = 256; K = 256;
        Bh = g_W0h; Bl = g_W0l; ldb = 256;
        bias = bias_in; C = g_out0; ldc = 256;
    } else if (mode == 1) {
        Ah = g_A0h + 128; Al = g_A0l + 128; lda = 256; K = 128;
        Bh = g_Wp0h; Bl = g_Wp0l; ldb = 256;
        bias = bias_in; C = g_res0; ldc = 256;
    } else {
        Ah = g_Hh; Al = g_Hl; lda = 256; K = 256;
        Bh = g_W1h; Bl = g_W1l; ldb = 384;
        bias = g_bias1; C = g_tuw; ldc = 384;
    }

    float acc[2][8][4];
#pragma unroll
    for (int i = 0; i < 2; i++) {
#pragma unroll
        for (int j = 0; j < 8; j++) {
#pragma unroll
            for (int q = 0; q < 4; q++) acc[i][j][q] = 0.f;
        }
    }

    const int S = K / 32;
    gemm_load_stage(sbase, tid, row0, 0, 0, Ah, Al, lda, Bh, Bl, ldb, col0);

    for (int s = 0; s < S; s++) {
        if (s + 1 < S) {
            gemm_load_stage(sbase, tid, row0, (s + 1) * 32, (s + 1) & 1, Ah, Al, lda, Bh, Bl, ldb, col0);
            asm volatile("cp.async.wait_group 1;\n" ::: "memory");
        } else {
            asm volatile("cp.async.wait_group 0;\n" ::: "memory");
        }
        __syncthreads();
        int stage = s & 1;
#pragma unroll
        for (int kk = 0; kk < 32; kk += 16) {
            unsigned int aH[2][4], aL[2][4];
#pragma unroll
            for (int mi = 0; mi < 2; mi++) {
                int r = wm * 32 + mi * 16 + (lane & 15);
                int cA = kk + ((lane >> 4) << 3);
                unsigned int ad = sbase + stage * A_STAGE_B + (unsigned int)(r * A_ST + cA) * 2;
                ldsm4(aH[mi], ad);
                ldsm4(aL[mi], ad + SM_AL_OFF);
            }
#pragma unroll
            for (int g = 0; g < 4; g++) {
                unsigned int bH[4], bL[4];
                int rB = kk + (lane & 15);
                int cB = wn * 64 + g * 16 + ((lane >> 4) << 3);
                unsigned int bd = sbase + SM_BH_OFF + stage * B_STAGE_B + (unsigned int)(rB * B_ST + cB) * 2;
                ldsm4t(bH, bd);
                ldsm4t(bL, bd + 2 * B_STAGE_B);
#pragma unroll
                for (int mi = 0; mi < 2; mi++) {
                    mma_bf16(acc[mi][2 * g], aH[mi], &bH[0]);
                    mma_bf16(acc[mi][2 * g], aL[mi], &bH[0]);
                    mma_bf16(acc[mi][2 * g], aH[mi], &bL[0]);
                    mma_bf16(acc[mi][2 * g + 1], aH[mi], &bH[2]);
                    mma_bf16(acc[mi][2 * g + 1], aL[mi], &bH[2]);
                    mma_bf16(acc[mi][2 * g + 1], aH[mi], &bL[2]);
                }
            }
        }
        __syncthreads();
    }

#pragma unroll
    for (int mi = 0; mi < 2; mi++) {
        int r0 = row0 + wm * 32 + mi * 16 + (lane >> 2);
#pragma unroll
        for (int nj = 0; nj < 8; nj++) {
            int c = col0 + wn * 64 + nj * 8 + 2 * (lane & 3);
            float b0 = bias[c];
            float b1 = bias[c + 1];
            if (r0 < NN) {
                float2 v = make_float2(acc[mi][nj][0] + b0, acc[mi][nj][1] + b1);
                *reinterpret_cast<float2*>(C + (size_t)r0 * ldc + c) = v;
            }
            if (r0 + 8 < NN) {
                float2 v = make_float2(acc[mi][nj][2] + b0, acc[mi][nj][3] + b1);
                *reinterpret_cast<float2*>(C + (size_t)(r0 + 8) * ldc + c) = v;
            }
        }
    }
}

// ---------------- fused row L2-norm + column stats (layer 0) ----------------
__global__ void k_norm_stats0() {
    int j = threadIdx.x; // 256
    __shared__ float wred[8];
    float s = 0.f, q = 0.f;
    for (int r = blockIdx.x; r < NN; r += gridDim.x) {
        float v = g_out0[r * H1 + j];
        float t = v * v;
#pragma unroll
        for (int o = 16; o > 0; o >>= 1) t += __shfl_xor_sync(0xffffffffu, t, o);
        int lane = j & 31;
        int w = j >> 5;
        if (lane == 0) wred[w] = t;
        __syncthreads();
        float tot = wred[0] + wred[1] + wred[2] + wred[3]
                  + wred[4] + wred[5] + wred[6] + wred[7];
        float inv = 1.f / fmaxf(sqrtf(tot), 1e-12f);
        v *= inv;
        g_out0[r * H1 + j] = v;
        s += v;
        q += v * v;
        __syncthreads();
    }
    atomicAdd(&g_sum0[j], s);
    atomicAdd(&g_sq0[j], q);
}

__global__ void k_colstats1() {
    int j = threadIdx.x; // 128
    float s = 0.f, q = 0.f;
    for (int r = blockIdx.x; r < NN; r += gridDim.x) {
        float v = g_out1[r * H2 + j];
        s += v;
        q += v * v;
    }
    atomicAdd(&g_sum1[j], s);
    atomicAdd(&g_sq1[j], q);
}

__global__ void k_bnprep(int mode, const float* __restrict__ g, const float* __restrict__ be) {
    int j = threadIdx.x;
    if (mode == 0) {
        if (j < H1) {
            float mu = g_sum0[j] / (float)NN;
            float var = g_sq0[j] / (float)NN - mu * mu;
            float s = g[j] * rsqrtf(var + 1e-5f);
            g_a0[j] = s;
            g_b0[j] = be[j] - mu * s;
        }
    } else {
        if (j < H2) {
            float mu = g_sum1[j] / (float)NN;
            float var = g_sq1[j] / (float)NN - mu * mu;
            float s = g[j] * rsqrtf(var + 1e-5f);
            g_a1[j] = s;
            g_b1[j] = be[j] - mu * s;
        }
    }
}

__global__ void k_bnapply0() {
    int i = blockIdx.x * blockDim.x + threadIdx.x;
    int stride = gridDim.x * blockDim.x;
    for (int t = i; t < NN * H1; t += stride) {
        int j = t & (H1 - 1);
        float v = g_a0[j] * g_out0[t] + g_b0[j];
        float h = fmaxf(v, 0.f) + g_res0[t];
        split_bf16(h, g_Hh[t], g_Hl[t]);
    }
}

__global__ void k_gcnt(const int* __restrict__ batch) {
    int i = blockIdx.x * blockDim.x + threadIdx.x;
    int stride = gridDim.x * blockDim.x;
    for (int t = i; t < NN; t += stride) atomicAdd(&g_gcnt[batch[t]], 1.f);
}

// BN+relu+residual layer 1, fused with chunked mean-pool accumulation.
__global__ void k_bnapply1(const int* __restrict__ batch) {
    __shared__ int bsh[128];
    int j = threadIdx.x; // 128
    int r0 = blockIdx.x * 128;
    int r1 = min(r0 + 128, NN);
    bsh[j] = (r0 + j < NN) ? batch[r0 + j] : -1;
    __syncthreads();
    float a = g_a1[j];
    float b = g_b1[j];
    float acc = 0.f;
    int cur = bsh[0];
    for (int r = r0; r < r1; r++) {
        int t = r * H2 + j;
        float v = fmaxf(a * g_out1[t] + b, 0.f) + g_tuw[r * 384 + 256 + j];
        int g = bsh[r - r0];
        if (g != cur) {
            atomicAdd(&g_embsum[cur * H2 + j], acc);
            acc = 0.f;
            cur = g;
        }
        acc += v;
    }
    atomicAdd(&g_embsum[cur * H2 + j], acc);
}

// ---------------- pool finalize + classifier MLP (single block) ----------------
__global__ __launch_bounds__(256) void k_classifier(
    const float* __restrict__ Wc0, const float* __restrict__ bc0,
    const float* __restrict__ gc0, const float* __restrict__ bec0,
    const float* __restrict__ Wc1, const float* __restrict__ bc1,
    const float* __restrict__ gc1, const float* __restrict__ bec1,
    const float* __restrict__ Wc2, const float* __restrict__ bc2,
    float* __restrict__ out)
{
    int tid = threadIdx.x;
    for (int t = tid; t < NG * H2; t += 256) {
        int gi = t >> 7;
        float c = fmaxf(g_gcnt[gi], 1.f);
        float v = g_embsum[t] / c;
        g_emb[t] = v;
        out[NG * 2 + t] = v;
    }
    __syncthreads();
    {
        int c = tid;
        float vals[64];
        float mu = 0.f, sq = 0.f;
#pragma unroll 4
        for (int r = 0; r < NG; r++) {
            float acc = bc0[c];
            for (int k = 0; k < H2; k++) acc += g_emb[r * H2 + k] * Wc0[k * 256 + c];
            vals[r] = acc;
            mu += acc;
            sq += acc * acc;
        }
        mu *= (1.f / NG);
        float var = sq * (1.f / NG) - mu * mu;
        float a = gc0[c] * rsqrtf(var + 1e-5f);
        float b = bec0[c] - mu * a;
        for (int r = 0; r < NG; r++) g_z0[r * 256 + c] = fmaxf(a * vals[r] + b, 0.f);
    }
    __syncthreads();
    if (tid < 128) {
        int c = tid;
        float vals[64];
        float mu = 0.f, sq = 0.f;
#pragma unroll 4
        for (int r = 0; r < NG; r++) {
            float acc = bc1[c];
            for (int k = 0; k < 256; k++) acc += g_z0[r * 256 + k] * Wc1[k * 128 + c];
            vals[r] = acc;
            mu += acc;
            sq += acc * acc;
        }
        mu *= (1.f / NG);
        float var = sq * (1.f / NG) - mu * mu;
        float a = gc1[c] * rsqrtf(var + 1e-5f);
        float b = bec1[c] - mu * a;
        for (int r = 0; r < NG; r++) g_z1[r * 128 + c] = fmaxf(a * vals[r] + b, 0.f);
    }
    __syncthreads();
    if (tid < NG * 2) {
        int gi = tid >> 1;
        int c = tid & 1;
        float acc = bc2[c];
        for (int k = 0; k < 128; k++) acc += g_z1[gi * 128 + k] * Wc2[k * 2 + c];
        out[gi * 2 + c] = acc;
    }
}

// ---------------- launch ----------------
extern "C" void kernel_launch(void* const* d_in, const int* in_sizes, int n_in,
                              void* d_out, int out_size) {
    const float* x    = (const float*)d_in[0];
    const int*   ei   = (const int*)d_in[1];
    const int*   batch= (const int*)d_in[2];
    const float* Wl0  = (const float*)d_in[3];
    const float* bl0  = (const float*)d_in[4];
    const float* Wr0  = (const float*)d_in[5];
    const float* g0   = (const float*)d_in[6];
    const float* be0  = (const float*)d_in[7];
    const float* Wl1  = (const float*)d_in[8];
    const float* bl1  = (const float*)d_in[9];
    const float* Wr1  = (const float*)d_in[10];
    const float* g1   = (const float*)d_in[11];
    const float* be1  = (const float*)d_in[12];
    const float* Wp0  = (const float*)d_in[13];
    const float* bp0  = (const float*)d_in[14];
    const float* Wp1  = (const float*)d_in[15];
    const float* bp1  = (const float*)d_in[16];
    const float* Wc0  = (const float*)d_in[17];
    const float* bc0  = (const float*)d_in[18];
    const float* gc0  = (const float*)d_in[19];
    const float* bec0 = (const float*)d_in[20];
    const float* Wc1  = (const float*)d_in[21];
    const float* bc1  = (const float*)d_in[22];
    const float* gc1  = (const float*)d_in[23];
    const float* bec1 = (const float*)d_in[24];
    const float* Wc2  = (const float*)d_in[25];
    const float* bc2  = (const float*)d_in[26];
    float* out = (float*)d_out;

    cudaFuncSetAttribute(k_gemm_bf16, cudaFuncAttributeMaxDynamicSharedMemorySize, SMEM_BYTES);

    const int MB = (NN + 127) / 128;  // 391

    k_zero<<<256, 256>>>();
    k_count<<<3125, 256>>>(ei);
    k_prep_weights<<<768, 256>>>(Wl0, Wr0, Wp0, Wl1, Wr1, Wp1, bl1, bp1);
    k_xcvt<<<4096, 256>>>(x);
    k_scan<<<1, 1024>>>();
    k_fill<<<3125, 256>>>(ei);

    // layer 0
    k_agg0<<<NN, 128>>>(x);
    k_gemm_bf16<<<dim3(2, MB), 256, SMEM_BYTES>>>(0, bl0);
    k_gemm_bf16<<<dim3(2, MB), 256, SMEM_BYTES>>>(1, bp0);
    k_norm_stats0<<<512, 256>>>();
    k_bnprep<<<1, 256>>>(0, g0, be0);
    k_bnapply0<<<4096, 256>>>();

    // layer 1: one GEMM for [t|u|res1] = h @ [Wl1|Wr1|Wp1] + [0|bl1|bp1]
    k_gemm_bf16<<<dim3(3, MB), 256, SMEM_BYTES>>>(2, nullptr);
    k_agg1<<<NN, 128>>>();
    k_colstats1<<<512, 128>>>();
    k_bnprep<<<1, 128>>>(1, g1, be1);

    // pool + classifier
    k_gcnt<<<196, 256>>>(batch);
    k_bnapply1<<<MB, 128>>>(batch);
    k_classifier<<<1, 256>>>(Wc0, bc0, gc0, bec0, Wc1, bc1, gc1, bec1, Wc2, bc2, out);
}

// round 5
// speedup vs baseline: 2.2724x; 1.7606x over previous
#include <cuda_runtime.h>
#include <cuda_bf16.h>
#include <cstdint>
#include <stdint.h>
#include <math.h>

#define NN 50000
#define EE 800000
#define DIN 128
#define H1 256
#define H2 128
#define NG 64
#define SCAN_BLKS 196

// ---------------- device scratch (static, allocation-free) ----------------
__device__ int   g_deg[NN];
__device__ int   g_rowptr[NN + 1];
__device__ int   g_cur[NN];
__device__ int   g_csrc[EE];
__device__ int   g_bsum[256];
__device__ int   g_boff[256];

// bf16-split activation buffers
__device__ __nv_bfloat16 g_A0h[NN * 256];   // cols 0-127: mean0, 128-255: x
__device__ __nv_bfloat16 g_A0l[NN * 256];
__device__ __nv_bfloat16 g_Hh[NN * 256];    // h (layer-0 output)
__device__ __nv_bfloat16 g_Hl[NN * 256];

// bf16-split weights (prepped each call)
__device__ __nv_bfloat16 g_W0h[256 * 256];
__device__ __nv_bfloat16 g_W0l[256 * 256];
__device__ __nv_bfloat16 g_Wp0h[128 * 256];
__device__ __nv_bfloat16 g_Wp0l[128 * 256];
__device__ __nv_bfloat16 g_W1h[256 * 384];
__device__ __nv_bfloat16 g_W1l[256 * 384];
__device__ float g_bias1[384];

// fp32 intermediates
__device__ float g_out0[NN * H1];
__device__ float g_res0[NN * H1];
__device__ float g_tuw[NN * 384];   // 0-127: t, 128-255: u, 256-383: res1
__device__ float g_out1[NN * H2];
__device__ float g_sum0[H1];
__device__ float g_sq0[H1];
__device__ float g_sum1[H2];
__device__ float g_sq1[H2];
__device__ float g_a0[H1];
__device__ float g_b0[H1];
__device__ float g_a1[H2];
__device__ float g_b1[H2];
__device__ float g_embsum[NG * H2];
__device__ float g_gcnt[NG];

__device__ __forceinline__ void split_bf16(float v, __nv_bfloat16& h, __nv_bfloat16& l) {
    h = __float2bfloat16(v);
    l = __float2bfloat16(v - __bfloat162float(h));
}

// pack 4 fp32 -> 4 bf16 hi (8B) + 4 bf16 lo (8B)
__device__ __forceinline__ void store_split4(const float* v, __nv_bfloat16* ph, __nv_bfloat16* pl) {
    union { __nv_bfloat16 b[4]; uint2 u; } Hh, Ll;
#pragma unroll
    for (int k = 0; k < 4; k++) split_bf16(v[k], Hh.b[k], Ll.b[k]);
    *reinterpret_cast<uint2*>(ph) = Hh.u;
    *reinterpret_cast<uint2*>(pl) = Ll.u;
}

// ---------------- init / CSR build ----------------
__global__ void k_zero() {
    int i = blockIdx.x * blockDim.x + threadIdx.x;
    int stride = gridDim.x * blockDim.x;
    for (int t = i; t < NN; t += stride) g_deg[t] = 0;
    for (int t = i; t < H1; t += stride) { g_sum0[t] = 0.f; g_sq0[t] = 0.f; }
    for (int t = i; t < H2; t += stride) { g_sum1[t] = 0.f; g_sq1[t] = 0.f; }
    for (int t = i; t < NG * H2; t += stride) g_embsum[t] = 0.f;
    for (int t = i; t < NG; t += stride) g_gcnt[t] = 0.f;
}

__global__ void k_count(const int* __restrict__ ei) {
    const int* dst = ei + EE;
    int i = blockIdx.x * blockDim.x + threadIdx.x;
    int stride = gridDim.x * blockDim.x;
    for (int e = i; e < EE; e += stride) atomicAdd(&g_deg[dst[e]], 1);
}

// phase A: per-block exclusive scan of deg, block totals to g_bsum
__global__ void k_scan_a() {
    __shared__ int ws[8];
    int tid = threadIdx.x;
    int lane = tid & 31;
    int w = tid >> 5;
    int idx = blockIdx.x * 256 + tid;
    int v = (idx < NN) ? g_deg[idx] : 0;
    int s = v;
#pragma unroll
    for (int o = 1; o < 32; o <<= 1) {
        int n = __shfl_up_sync(0xffffffffu, s, o);
        if (lane >= o) s += n;
    }
    if (lane == 31) ws[w] = s;
    __syncthreads();
    if (tid < 8) {
        int t = ws[tid];
#pragma unroll
        for (int o = 1; o < 8; o <<= 1) {
            int n = __shfl_up_sync(0xffu, t, o);
            if (tid >= o) t += n;
        }
        ws[tid] = t;
    }
    __syncthreads();
    int incl = s + (w > 0 ? ws[w - 1] : 0);
    if (idx < NN) g_rowptr[idx] = incl - v;
    if (tid == 255) g_bsum[blockIdx.x] = incl;
}

// phase B: scan block totals
__global__ void k_scan_b() {
    __shared__ int ws[8];
    int tid = threadIdx.x;
    int lane = tid & 31;
    int w = tid >> 5;
    int v = (tid < SCAN_BLKS) ? g_bsum[tid] : 0;
    int s = v;
#pragma unroll
    for (int o = 1; o < 32; o <<= 1) {
        int n = __shfl_up_sync(0xffffffffu, s, o);
        if (lane >= o) s += n;
    }
    if (lane == 31) ws[w] = s;
    __syncthreads();
    if (tid < 8) {
        int t = ws[tid];
#pragma unroll
        for (int o = 1; o < 8; o <<= 1) {
            int n = __shfl_up_sync(0xffu, t, o);
            if (tid >= o) t += n;
        }
        ws[tid] = t;
    }
    __syncthreads();
    int incl = s + (w > 0 ? ws[w - 1] : 0);
    if (tid < SCAN_BLKS) g_boff[tid] = incl - v;
    if (tid == 255) g_rowptr[NN] = incl;
}

// phase C: add block offsets, init cursor
__global__ void k_scan_c() {
    int idx = blockIdx.x * 256 + threadIdx.x;
    if (idx < NN) {
        int rp = g_rowptr[idx] + g_boff[blockIdx.x];
        g_rowptr[idx] = rp;
        g_cur[idx] = rp;
    }
}

__global__ void k_fill(const int* __restrict__ ei) {
    const int* src = ei;
    const int* dst = ei + EE;
    int i = blockIdx.x * blockDim.x + threadIdx.x;
    int stride = gridDim.x * blockDim.x;
    for (int e = i; e < EE; e += stride) {
        int d = dst[e];
        int slot = atomicAdd(&g_cur[d], 1);
        g_csrc[slot] = src[e];
    }
}

// ---------------- weight prep ----------------
__global__ void k_prep_weights(
    const float* __restrict__ Wl0, const float* __restrict__ Wr0,
    const float* __restrict__ Wp0,
    const float* __restrict__ Wl1, const float* __restrict__ Wr1,
    const float* __restrict__ Wp1,
    const float* __restrict__ bl1, const float* __restrict__ bp1)
{
    int i = blockIdx.x * blockDim.x + threadIdx.x;
    int stride = gridDim.x * blockDim.x;
    const int T0 = 256 * 256;
    const int T1 = 128 * 256;
    const int T2 = 256 * 384;
    for (int t = i; t < T0 + T1 + T2; t += stride) {
        if (t < T0) {
            int r = t >> 8;
            int c = t & 255;
            float v = (r < 128) ? Wl0[r * 256 + c] : Wr0[(r - 128) * 256 + c];
            split_bf16(v, g_W0h[t], g_W0l[t]);
        } else if (t < T0 + T1) {
            int j = t - T0;
            split_bf16(Wp0[j], g_Wp0h[j], g_Wp0l[j]);
        } else {
            int j = t - T0 - T1;
            int r = j / 384;
            int c = j % 384;
            float v;
            if (c < 128) v = Wl1[r * 128 + c];
            else if (c < 256) v = Wr1[r * 128 + (c - 128)];
            else v = Wp1[r * 128 + (c - 256)];
            split_bf16(v, g_W1h[j], g_W1l[j]);
        }
    }
    for (int t = i; t < 384; t += stride) {
        float v;
        if (t < 128) v = 0.f;
        else if (t < 256) v = bl1[t - 128];
        else v = bp1[t - 256];
        g_bias1[t] = v;
    }
}

// ---------------- aggregation (warp per node) ----------------
// layer 0: mean over neighbors of x -> A0 cols 0..127; fused x -> cols 128..255
__global__ void k_agg0(const float* __restrict__ x) {
    int gw = (blockIdx.x * blockDim.x + threadIdx.x) >> 5;
    int lane = threadIdx.x & 31;
    int nw = (gridDim.x * blockDim.x) >> 5;
    for (int r = gw; r < NN; r += nw) {
        int s = g_rowptr[r];
        int e = g_rowptr[r + 1];
        float4 acc = make_float4(0.f, 0.f, 0.f, 0.f);
        for (int p = s; p < e; p += 32) {
            int cnt = min(e - p, 32);
            int myidx = (lane < cnt) ? g_csrc[p + lane] : 0;
#pragma unroll 4
            for (int q = 0; q < cnt; q++) {
                int nbr = __shfl_sync(0xffffffffu, myidx, q);
                float4 xv = *reinterpret_cast<const float4*>(&x[nbr * DIN + lane * 4]);
                acc.x += xv.x; acc.y += xv.y; acc.z += xv.z; acc.w += xv.w;
            }
        }
        float inv = 1.f / (float)max(e - s, 1);
        float mv[4] = {acc.x * inv, acc.y * inv, acc.z * inv, acc.w * inv};
        store_split4(mv, &g_A0h[r * 256 + lane * 4], &g_A0l[r * 256 + lane * 4]);
        float4 xr = *reinterpret_cast<const float4*>(&x[r * DIN + lane * 4]);
        float xv4[4] = {xr.x, xr.y, xr.z, xr.w};
        store_split4(xv4, &g_A0h[r * 256 + 128 + lane * 4], &g_A0l[r * 256 + 128 + lane * 4]);
    }
}

// layer 1: aggregate t, add u, row L2-normalize -> out1
__global__ void k_agg1() {
    int gw = (blockIdx.x * blockDim.x + threadIdx.x) >> 5;
    int lane = threadIdx.x & 31;
    int nw = (gridDim.x * blockDim.x) >> 5;
    for (int r = gw; r < NN; r += nw) {
        int s = g_rowptr[r];
        int e = g_rowptr[r + 1];
        float4 acc = make_float4(0.f, 0.f, 0.f, 0.f);
        for (int p = s; p < e; p += 32) {
            int cnt = min(e - p, 32);
            int myidx = (lane < cnt) ? g_csrc[p + lane] : 0;
#pragma unroll 4
            for (int q = 0; q < cnt; q++) {
                int nbr = __shfl_sync(0xffffffffu, myidx, q);
                float4 tv = *reinterpret_cast<const float4*>(&g_tuw[nbr * 384 + lane * 4]);
                acc.x += tv.x; acc.y += tv.y; acc.z += tv.z; acc.w += tv.w;
            }
        }
        float invd = 1.f / (float)max(e - s, 1);
        float4 uv = *reinterpret_cast<const float4*>(&g_tuw[r * 384 + 128 + lane * 4]);
        float4 v;
        v.x = acc.x * invd + uv.x;
        v.y = acc.y * invd + uv.y;
        v.z = acc.z * invd + uv.z;
        v.w = acc.w * invd + uv.w;
        float q = v.x * v.x + v.y * v.y + v.z * v.z + v.w * v.w;
#pragma unroll
        for (int o = 16; o > 0; o >>= 1) q += __shfl_xor_sync(0xffffffffu, q, o);
        float inv = 1.f / fmaxf(sqrtf(q), 1e-12f);
        v.x *= inv; v.y *= inv; v.z *= inv; v.w *= inv;
        *reinterpret_cast<float4*>(&g_out1[r * H2 + lane * 4]) = v;
    }
}

// ---------------- bf16-split tensor-core GEMM (unchanged, proven) ----------------
#define A_ST 40
#define B_ST 136
#define A_STAGE_B (128 * A_ST * 2)
#define B_STAGE_B (32 * B_ST * 2)
#define SM_AL_OFF (2 * A_STAGE_B)
#define SM_BH_OFF (4 * A_STAGE_B)
#define SMEM_BYTES (SM_BH_OFF + 4 * B_STAGE_B)

__device__ __forceinline__ void cp16(unsigned int dst, const void* src, bool p) {
    int sz = p ? 16 : 0;
    asm volatile("cp.async.cg.shared.global [%0], [%1], 16, %2;\n"
                 :: "r"(dst), "l"(src), "r"(sz));
}
__device__ __forceinline__ void ldsm4(unsigned int* r, unsigned int a) {
    asm volatile("ldmatrix.sync.aligned.m8n8.x4.shared.b16 {%0,%1,%2,%3}, [%4];"
                 : "=r"(r[0]), "=r"(r[1]), "=r"(r[2]), "=r"(r[3]) : "r"(a));
}
__device__ __forceinline__ void ldsm4t(unsigned int* r, unsigned int a) {
    asm volatile("ldmatrix.sync.aligned.m8n8.x4.trans.shared.b16 {%0,%1,%2,%3}, [%4];"
                 : "=r"(r[0]), "=r"(r[1]), "=r"(r[2]), "=r"(r[3]) : "r"(a));
}
__device__ __forceinline__ void mma_bf16(float* d, const unsigned int* a, const unsigned int* b) {
    asm volatile("mma.sync.aligned.m16n8k16.row.col.f32.bf16.bf16.f32 "
                 "{%0,%1,%2,%3}, {%4,%5,%6,%7}, {%8,%9}, {%0,%1,%2,%3};"
                 : "+f"(d[0]), "+f"(d[1]), "+f"(d[2]), "+f"(d[3])
                 : "r"(a[0]), "r"(a[1]), "r"(a[2]), "r"(a[3]), "r"(b[0]), "r"(b[1]));
}

__device__ __forceinline__ void gemm_load_stage(
    unsigned int sbase, int tid, int row0, int k0, int stage,
    const __nv_bfloat16* Ah, const __nv_bfloat16* Al, int lda,
    const __nv_bfloat16* Bh, const __nv_bfloat16* Bl, int ldb, int col0)
{
#pragma unroll
    for (int i = 0; i < 2; i++) {
        int c = tid + i * 256;
        int row = c >> 2;
        int seg = c & 3;
        int gr = row0 + row;
        bool p = gr < NN;
        size_t goff = (size_t)(p ? gr : 0) * lda + k0 + seg * 8;
        unsigned int d = sbase + stage * A_STAGE_B + (unsigned int)(row * A_ST + seg * 8) * 2;
        cp16(d, Ah + goff, p);
        cp16(d + SM_AL_OFF, Al + goff, p);
    }
#pragma unroll
    for (int i = 0; i < 2; i++) {
        int c = tid + i * 256;
        int row = c >> 4;
        int seg = c & 15;
        size_t goff = (size_t)(k0 + row) * ldb + col0 + seg * 8;
        unsigned int d = sbase + SM_BH_OFF + stage * B_STAGE_B + (unsigned int)(row * B_ST + seg * 8) * 2;
        cp16(d, Bh + goff, true);
        cp16(d + 2 * B_STAGE_B, Bl + goff, true);
    }
    asm volatile("cp.async.commit_group;\n" ::: "memory");
}

__global__ __launch_bounds__(256) void k_gemm_bf16(int mode, const float* __restrict__ bias_in) {
    extern __shared__ __align__(16) char sm[];
    const int tid = threadIdx.x;
    const int lane = tid & 31;
    const int warp = tid >> 5;
    const int wm = warp & 3;
    const int wn = warp >> 2;
    const int row0 = blockIdx.y * 128;
    const int col0 = blockIdx.x * 128;
    unsigned int sbase = (unsigned int)__cvta_generic_to_shared(sm);

    const __nv_bfloat16* Ah;
    const __nv_bfloat16* Al;
    const __nv_bfloat16* Bh;
    const __nv_bfloat16* Bl;
    const float* bias;
    float* C;
    int lda, ldb, ldc, K;
    if (mode == 0) {
        Ah = g_A0h; Al = g_A0l; lda = 256; K = 256;
        Bh = g_W0h; Bl = g_W0l; ldb = 256;
        bias = bias_in; C = g_out0; ldc = 256;
    } else if (mode == 1) {
        Ah = g_A0h + 128; Al = g_A0l + 128; lda = 256; K = 128;
        Bh = g_Wp0h; Bl = g_Wp0l; ldb = 256;
        bias = bias_in; C = g_res0; ldc = 256;
    } else {
        Ah = g_Hh; Al = g_Hl; lda = 256; K = 256;
        Bh = g_W1h; Bl = g_W1l; ldb = 384;
        bias = g_bias1; C = g_tuw; ldc = 384;
    }

    float acc[2][8][4];
#pragma unroll
    for (int i = 0; i < 2; i++) {
#pragma unroll
        for (int j = 0; j < 8; j++) {
#pragma unroll
            for (int q = 0; q < 4; q++) acc[i][j][q] = 0.f;
        }
    }

    const int S = K / 32;
    gemm_load_stage(sbase, tid, row0, 0, 0, Ah, Al, lda, Bh, Bl, ldb, col0);

    for (int s = 0; s < S; s++) {
        if (s + 1 < S) {
            gemm_load_stage(sbase, tid, row0, (s + 1) * 32, (s + 1) & 1, Ah, Al, lda, Bh, Bl, ldb, col0);
            asm volatile("cp.async.wait_group 1;\n" ::: "memory");
        } else {
            asm volatile("cp.async.wait_group 0;\n" ::: "memory");
        }
        __syncthreads();
        int stage = s & 1;
#pragma unroll
        for (int kk = 0; kk < 32; kk += 16) {
            unsigned int aH[2][4], aL[2][4];
#pragma unroll
            for (int mi = 0; mi < 2; mi++) {
                int r = wm * 32 + mi * 16 + (lane & 15);
                int cA = kk + ((lane >> 4) << 3);
                unsigned int ad = sbase + stage * A_STAGE_B + (unsigned int)(r * A_ST + cA) * 2;
                ldsm4(aH[mi], ad);
                ldsm4(aL[mi], ad + SM_AL_OFF);
            }
#pragma unroll
            for (int g = 0; g < 4; g++) {
                unsigned int bH[4], bL[4];
                int rB = kk + (lane & 15);
                int cB = wn * 64 + g * 16 + ((lane >> 4) << 3);
                unsigned int bd = sbase + SM_BH_OFF + stage * B_STAGE_B + (unsigned int)(rB * B_ST + cB) * 2;
                ldsm4t(bH, bd);
                ldsm4t(bL, bd + 2 * B_STAGE_B);
#pragma unroll
                for (int mi = 0; mi < 2; mi++) {
                    mma_bf16(acc[mi][2 * g], aH[mi], &bH[0]);
                    mma_bf16(acc[mi][2 * g], aL[mi], &bH[0]);
                    mma_bf16(acc[mi][2 * g], aH[mi], &bL[0]);
                    mma_bf16(acc[mi][2 * g + 1], aH[mi], &bH[2]);
                    mma_bf16(acc[mi][2 * g + 1], aL[mi], &bH[2]);
                    mma_bf16(acc[mi][2 * g + 1], aH[mi], &bL[2]);
                }
            }
        }
        __syncthreads();
    }

#pragma unroll
    for (int mi = 0; mi < 2; mi++) {
        int r0 = row0 + wm * 32 + mi * 16 + (lane >> 2);
#pragma unroll
        for (int nj = 0; nj < 8; nj++) {
            int c = col0 + wn * 64 + nj * 8 + 2 * (lane & 3);
            float b0 = bias[c];
            float b1 = bias[c + 1];
            if (r0 < NN) {
                float2 v = make_float2(acc[mi][nj][0] + b0, acc[mi][nj][1] + b1);
                *reinterpret_cast<float2*>(C + (size_t)r0 * ldc + c) = v;
            }
            if (r0 + 8 < NN) {
                float2 v = make_float2(acc[mi][nj][2] + b0, acc[mi][nj][3] + b1);
                *reinterpret_cast<float2*>(C + (size_t)(r0 + 8) * ldc + c) = v;
            }
        }
    }
}

// ---------------- fused row L2-norm + column stats (layer 0), warp per row ----------------
__global__ void k_norm_stats0() {
    __shared__ float ssum[256];
    __shared__ float ssq[256];
    int tid = threadIdx.x;
    int lane = tid & 31;
    int gw = (blockIdx.x * blockDim.x + tid) >> 5;
    int nw = (gridDim.x * blockDim.x) >> 5;
    ssum[tid] = 0.f;
    ssq[tid] = 0.f;
    __syncthreads();
    float s[8], q[8];
#pragma unroll
    for (int k = 0; k < 8; k++) { s[k] = 0.f; q[k] = 0.f; }
    for (int r = gw; r < NN; r += nw) {
        float4 v0 = *reinterpret_cast<const float4*>(&g_out0[r * H1 + lane * 8]);
        float4 v1 = *reinterpret_cast<const float4*>(&g_out0[r * H1 + lane * 8 + 4]);
        float t = v0.x * v0.x + v0.y * v0.y + v0.z * v0.z + v0.w * v0.w
                + v1.x * v1.x + v1.y * v1.y + v1.z * v1.z + v1.w * v1.w;
#pragma unroll
        for (int o = 16; o > 0; o >>= 1) t += __shfl_xor_sync(0xffffffffu, t, o);
        float inv = 1.f / fmaxf(sqrtf(t), 1e-12f);
        float v[8] = {v0.x * inv, v0.y * inv, v0.z * inv, v0.w * inv,
                      v1.x * inv, v1.y * inv, v1.z * inv, v1.w * inv};
        *reinterpret_cast<float4*>(&g_out0[r * H1 + lane * 8]) = make_float4(v[0], v[1], v[2], v[3]);
        *reinterpret_cast<float4*>(&g_out0[r * H1 + lane * 8 + 4]) = make_float4(v[4], v[5], v[6], v[7]);
#pragma unroll
        for (int k = 0; k < 8; k++) { s[k] += v[k]; q[k] += v[k] * v[k]; }
    }
#pragma unroll
    for (int k = 0; k < 8; k++) {
        atomicAdd(&ssum[lane * 8 + k], s[k]);
        atomicAdd(&ssq[lane * 8 + k], q[k]);
    }
    __syncthreads();
    atomicAdd(&g_sum0[tid], ssum[tid]);
    atomicAdd(&g_sq0[tid], ssq[tid]);
}

__global__ void k_colstats1() {
    int j = threadIdx.x; // 128
    float s = 0.f, q = 0.f;
    for (int r = blockIdx.x; r < NN; r += gridDim.x) {
        float v = g_out1[r * H2 + j];
        s += v;
        q += v * v;
    }
    atomicAdd(&g_sum1[j], s);
    atomicAdd(&g_sq1[j], q);
}

__global__ void k_bnprep(int mode, const float* __restrict__ g, const float* __restrict__ be) {
    int j = threadIdx.x;
    if (mode == 0) {
        if (j < H1) {
            float mu = g_sum0[j] / (float)NN;
            float var = g_sq0[j] / (float)NN - mu * mu;
            float s = g[j] * rsqrtf(var + 1e-5f);
            g_a0[j] = s;
            g_b0[j] = be[j] - mu * s;
        }
    } else {
        if (j < H2) {
            float mu = g_sum1[j] / (float)NN;
            float var = g_sq1[j] / (float)NN - mu * mu;
            float s = g[j] * rsqrtf(var + 1e-5f);
            g_a1[j] = s;
            g_b1[j] = be[j] - mu * s;
        }
    }
}

// BN + relu + residual layer 0 -> h bf16 split (float4)
__global__ void k_bnapply0() {
    int i = blockIdx.x * blockDim.x + threadIdx.x;
    int stride = gridDim.x * blockDim.x;
    const int T4 = NN * H1 / 4;
    for (int t = i; t < T4; t += stride) {
        int col = (t & 63) * 4;
        float4 o = reinterpret_cast<const float4*>(g_out0)[t];
        float4 rs = reinterpret_cast<const float4*>(g_res0)[t];
        float4 a = *reinterpret_cast<const float4*>(&g_a0[col]);
        float4 b = *reinterpret_cast<const float4*>(&g_b0[col]);
        float h[4];
        h[0] = fmaxf(a.x * o.x + b.x, 0.f) + rs.x;
        h[1] = fmaxf(a.y * o.y + b.y, 0.f) + rs.y;
        h[2] = fmaxf(a.z * o.z + b.z, 0.f) + rs.z;
        h[3] = fmaxf(a.w * o.w + b.w, 0.f) + rs.w;
        store_split4(h, &g_Hh[t * 4], &g_Hl[t * 4]);
    }
}

__global__ void k_gcnt(const int* __restrict__ batch) {
    int i = blockIdx.x * blockDim.x + threadIdx.x;
    int stride = gridDim.x * blockDim.x;
    for (int t = i; t < NN; t += stride) atomicAdd(&g_gcnt[batch[t]], 1.f);
}

// BN+relu+residual layer 1, fused with chunked mean-pool accumulation.
__global__ void k_bnapply1(const int* __restrict__ batch) {
    __shared__ int bsh[128];
    int j = threadIdx.x; // 128
    int r0 = blockIdx.x * 128;
    int r1 = min(r0 + 128, NN);
    bsh[j] = (r0 + j < NN) ? batch[r0 + j] : -1;
    __syncthreads();
    float a = g_a1[j];
    float b = g_b1[j];
    float acc = 0.f;
    int cur = bsh[0];
    for (int r = r0; r < r1; r++) {
        int t = r * H2 + j;
        float v = fmaxf(a * g_out1[t] + b, 0.f) + g_tuw[r * 384 + 256 + j];
        int g = bsh[r - r0];
        if (g != cur) {
            atomicAdd(&g_embsum[cur * H2 + j], acc);
            acc = 0.f;
            cur = g;
        }
        acc += v;
    }
    atomicAdd(&g_embsum[cur * H2 + j], acc);
}

// ---------------- classifier: shared-memory, register-blocked ----------------
#define CLS_SMEM ((NG * H2 + NG * 256) * 4)   // emb 32KB + z0 64KB = 96KB

__global__ __launch_bounds__(256) void k_classifier(
    const float* __restrict__ Wc0, const float* __restrict__ bc0,
    const float* __restrict__ gc0, const float* __restrict__ bec0,
    const float* __restrict__ Wc1, const float* __restrict__ bc1,
    const float* __restrict__ gc1, const float* __restrict__ bec1,
    const float* __restrict__ Wc2, const float* __restrict__ bc2,
    float* __restrict__ out)
{
    extern __shared__ float smf[];
    float* embsh = smf;             // [64][128]; reused as z1 [64][128] after c0 inputs done
    float* z0sh = smf + NG * H2;    // [64][256]
    int tid = threadIdx.x;

    // finalize emb = sum / max(cnt,1); also write to out[128..]
    for (int t = tid; t < NG * H2; t += 256) {
        int gi = t >> 7;
        float c = fmaxf(g_gcnt[gi], 1.f);
        float v = g_embsum[t] / c;
        embsh[t] = v;
        out[NG * 2 + t] = v;
    }
    __syncthreads();

    // ---- c0: z0 = emb[64,128] @ Wc0[128,256] + bc0 ----
    {
        int cg = tid & 63;          // 64 col groups of 4
        int rg = tid >> 6;          // 4 row groups of 16
        int c = cg * 4;
        int r0 = rg * 16;
        float acc[16][4];
#pragma unroll
        for (int rr = 0; rr < 16; rr++)
#pragma unroll
            for (int qq = 0; qq < 4; qq++) acc[rr][qq] = 0.f;
        for (int k = 0; k < H2; k++) {
            float4 w = *reinterpret_cast<const float4*>(&Wc0[k * 256 + c]);
#pragma unroll
            for (int rr = 0; rr < 16; rr++) {
                float a = embsh[(r0 + rr) * H2 + k];
                acc[rr][0] += a * w.x;
                acc[rr][1] += a * w.y;
                acc[rr][2] += a * w.z;
                acc[rr][3] += a * w.w;
            }
        }
        float4 bi = *reinterpret_cast<const float4*>(&bc0[c]);
#pragma unroll
        for (int rr = 0; rr < 16; rr++) {
            float4 v = make_float4(acc[rr][0] + bi.x, acc[rr][1] + bi.y,
                                   acc[rr][2] + bi.z, acc[rr][3] + bi.w);
            *reinterpret_cast<float4*>(&z0sh[(r0 + rr) * 256 + c]) = v;
        }
    }
    __syncthreads();
    // BN + relu per column (256 threads, one col each)
    {
        float mu = 0.f, sq = 0.f;
#pragma unroll 8
        for (int r = 0; r < NG; r++) {
            float v = z0sh[r * 256 + tid];
            mu += v;
            sq += v * v;
        }
        mu *= (1.f / NG);
        float var = sq * (1.f / NG) - mu * mu;
        float a = gc0[tid] * rsqrtf(var + 1e-5f);
        float b = bec0[tid] - mu * a;
#pragma unroll 8
        for (int r = 0; r < NG; r++)
            z0sh[r * 256 + tid] = fmaxf(a * z0sh[r * 256 + tid] + b, 0.f);
    }
    __syncthreads();

    // ---- c1: z1 = z0[64,256] @ Wc1[256,128] + bc1 (z1 overwrites embsh) ----
    {
        int cg = tid & 31;          // 32 col groups of 4
        int rg = tid >> 5;          // 8 row groups of 8
        int c = cg * 4;
        int r0 = rg * 8;
        float acc[8][4];
#pragma unroll
        for (int rr = 0; rr < 8; rr++)
#pragma unroll
            for (int qq = 0; qq < 4; qq++) acc[rr][qq] = 0.f;
        for (int k = 0; k < 256; k++) {
            float4 w = *reinterpret_cast<const float4*>(&Wc1[k * 128 + c]);
#pragma unroll
            for (int rr = 0; rr < 8; rr++) {
                float a = z0sh[(r0 + rr) * 256 + k];
                acc[rr][0] += a * w.x;
                acc[rr][1] += a * w.y;
                acc[rr][2] += a * w.z;
                acc[rr][3] += a * w.w;
            }
        }
        float4 bi = *reinterpret_cast<const float4*>(&bc1[c]);
#pragma unroll
        for (int rr = 0; rr < 8; rr++) {
            float4 v = make_float4(acc[rr][0] + bi.x, acc[rr][1] + bi.y,
                                   acc[rr][2] + bi.z, acc[rr][3] + bi.w);
            *reinterpret_cast<float4*>(&embsh[(r0 + rr) * 128 + c]) = v;
        }
    }
    __syncthreads();
    // BN + relu per column (first 128 threads)
    if (tid < 128) {
        float mu = 0.f, sq = 0.f;
#pragma unroll 8
        for (int r = 0; r < NG; r++) {
            float v = embsh[r * 128 + tid];
            mu += v;
            sq += v * v;
        }
        mu *= (1.f / NG);
        float var = sq * (1.f / NG) - mu * mu;
        float a = gc1[tid] * rsqrtf(var + 1e-5f);
        float b = bec1[tid] - mu * a;
#pragma unroll 8
        for (int r = 0; r < NG; r++)
            embsh[r * 128 + tid] = fmaxf(a * embsh[r * 128 + tid] + b, 0.f);
    }
    __syncthreads();

    // ---- c2: logits = z1 @ Wc2 + bc2 ----
    if (tid < NG * 2) {
        int gi = tid >> 1;
        int c = tid & 1;
        float acc = bc2[c];
        for (int k = 0; k < 128; k++) acc += embsh[gi * 128 + k] * Wc2[k * 2 + c];
        out[gi * 2 + c] = acc;
    }
}

// ---------------- launch ----------------
extern "C" void kernel_launch(void* const* d_in, const int* in_sizes, int n_in,
                              void* d_out, int out_size) {
    const float* x    = (const float*)d_in[0];
    const int*   ei   = (const int*)d_in[1];
    const int*   batch= (const int*)d_in[2];
    const float* Wl0  = (const float*)d_in[3];
    const float* bl0  = (const float*)d_in[4];
    const float* Wr0  = (const float*)d_in[5];
    const float* g0   = (const float*)d_in[6];
    const float* be0  = (const float*)d_in[7];
    const float* Wl1  = (const float*)d_in[8];
    const float* bl1  = (const float*)d_in[9];
    const float* Wr1  = (const float*)d_in[10];
    const float* g1   = (const float*)d_in[11];
    const float* be1  = (const float*)d_in[12];
    const float* Wp0  = (const float*)d_in[13];
    const float* bp0  = (const float*)d_in[14];
    const float* Wp1  = (const float*)d_in[15];
    const float* bp1  = (const float*)d_in[16];
    const float* Wc0  = (const float*)d_in[17];
    const float* bc0  = (const float*)d_in[18];
    const float* gc0  = (const float*)d_in[19];
    const float* bec0 = (const float*)d_in[20];
    const float* Wc1  = (const float*)d_in[21];
    const float* bc1  = (const float*)d_in[22];
    const float* gc1  = (const float*)d_in[23];
    const float* bec1 = (const float*)d_in[24];
    const float* Wc2  = (const float*)d_in[25];
    const float* bc2  = (const float*)d_in[26];
    float* out = (float*)d_out;

    cudaFuncSetAttribute(k_gemm_bf16, cudaFuncAttributeMaxDynamicSharedMemorySize, SMEM_BYTES);
    cudaFuncSetAttribute(k_classifier, cudaFuncAttributeMaxDynamicSharedMemorySize, CLS_SMEM);

    const int MB = (NN + 127) / 128;  // 391

    k_zero<<<256, 256>>>();
    k_count<<<3125, 256>>>(ei);
    k_prep_weights<<<768, 256>>>(Wl0, Wr0, Wp0, Wl1, Wr1, Wp1, bl1, bp1);
    k_scan_a<<<SCAN_BLKS, 256>>>();
    k_scan_b<<<1, 256>>>();
    k_scan_c<<<SCAN_BLKS, 256>>>();
    k_fill<<<3125, 256>>>(ei);

    // layer 0
    k_agg0<<<512, 256>>>(x);
    k_gemm_bf16<<<dim3(2, MB), 256, SMEM_BYTES>>>(0, bl0);
    k_gemm_bf16<<<dim3(2, MB), 256, SMEM_BYTES>>>(1, bp0);
    k_norm_stats0<<<256, 256>>>();
    k_bnprep<<<1, 256>>>(0, g0, be0);
    k_bnapply0<<<2048, 256>>>();

    // layer 1
    k_gemm_bf16<<<dim3(3, MB), 256, SMEM_BYTES>>>(2, nullptr);
    k_agg1<<<512, 256>>>();
    k_colstats1<<<512, 128>>>();
    k_bnprep<<<1, 128>>>(1, g1, be1);

    // pool + classifier
    k_gcnt<<<196, 256>>>(batch);
    k_bnapply1<<<MB, 128>>>(batch);
    k_classifier<<<1, 256, CLS_SMEM>>>(Wc0, bc0, gc0, bec0, Wc1, bc1, gc1, bec1, Wc2, bc2, out);
}